// round 14
// baseline (speedup 1.0000x reference)
#include <cuda_runtime.h>
#include <math.h>

// Problem constants
constexpr int Bc  = 4;
constexpr int Sc  = 2048;
constexpr int Dc  = 1024;
constexpr int Hc  = 16;
constexpr int HDc = 64;
constexpr int Mrows = Bc * Sc;                 // 8192
constexpr int QKV_ELEMS = Bc * Sc * Dc;        // 8388608 ([B,S,D] layout)
constexpr int O_ELEMS   = Bc * Sc * Dc;        // 8388608

// Scratch (no allocation allowed -> __device__ globals)
// q/k/v stored as [B,S,D] = [B,S,H*HD]: head h occupies columns h*64..h*64+63.
__device__ float g_q[QKV_ELEMS];
__device__ float g_k[QKV_ELEMS];
__device__ float g_v[QKV_ELEMS];
__device__ float g_o[O_ELEMS];     // [B,S,D] (heads concatenated)

// ---------------------------------------------------------------------------
// SGEMM: C[8192x1024] = A[8192x1024] @ B[1024x1024] + bias[1024]
// GATHER=true:  B[d][c] = W[c>>6][d][c&63]   (W is [H][D][HD], per-head proj)
// GATHER=false: B[d][c] = Bm[d*1024 + c]     (plain row-major Wp)
// 128x128 block tile, 256 threads, 8x8 per thread (4+4 split fragments),
// k-chunk 8, register prefetch of next chunk.
// grid = (Mrows/128, Dc/128)
// ---------------------------------------------------------------------------
template <bool GATHER>
__global__ __launch_bounds__(256) void gemm_kernel(
    const float* __restrict__ A,
    const float* __restrict__ Bm,
    const float* __restrict__ bias,
    float* __restrict__ C)
{
    const int m0 = blockIdx.x * 128;
    const int c0 = blockIdx.y * 128;

    __shared__ __align__(16) float Xs[8][128];   // [k][row]
    __shared__ __align__(16) float Bs[8][132];   // [k][col] (pad 132, 16B-aligned rows)

    const int tid = threadIdx.x;
    const int tx = tid & 15;          // column group 0..15
    const int ty = tid >> 4;          // row group 0..15

    // X loader: 128 rows x 8 k = 1024 floats; thread -> row tid>>1, k-half (tid&1)*4
    const int xrow = tid >> 1;
    const int xk   = (tid & 1) * 4;
    // B loader: 8 k x 128 c; thread -> k tid>>5, col (tid&31)*4
    const int bk   = tid >> 5;
    const int bc   = (tid & 31) * 4;

    float acc[8][8] = {};

    // ---- global load helpers -------------------------------------------------
    const float* Aptr = &A[(size_t)(m0 + xrow) * Dc + xk];
    // B address for (d = k0+bk, c = c0+bc): gathered or plain.
    const int ccol = c0 + bc;
    const float* Bbase;
    size_t bstride;   // float advance per +1 in d
    if (GATHER) {
        // W[h][d][e]: &W[(c>>6)*D*64 + d*64 + (c&63)], d-stride = 64
        Bbase   = &Bm[(size_t)(ccol >> 6) * Dc * HDc + (size_t)bk * HDc + (ccol & 63)];
        bstride = HDc;
    } else {
        Bbase   = &Bm[(size_t)bk * Dc + ccol];
        bstride = Dc;
    }

    float4 xr = *reinterpret_cast<const float4*>(Aptr);
    float4 br = *reinterpret_cast<const float4*>(Bbase);

    for (int k0 = 0; k0 < Dc; k0 += 8) {
        // stage prefetched regs into smem
        Xs[xk + 0][xrow] = xr.x; Xs[xk + 1][xrow] = xr.y;
        Xs[xk + 2][xrow] = xr.z; Xs[xk + 3][xrow] = xr.w;
        *reinterpret_cast<float4*>(&Bs[bk][bc]) = br;
        __syncthreads();

        // prefetch next chunk (overlaps with compute below)
        if (k0 + 8 < Dc) {
            xr = *reinterpret_cast<const float4*>(Aptr + (k0 + 8));
            br = *reinterpret_cast<const float4*>(Bbase + (size_t)(k0 + 8) * bstride);
        }

        #pragma unroll
        for (int k = 0; k < 8; ++k) {
            float4 a0 = *reinterpret_cast<const float4*>(&Xs[k][ty * 4]);
            float4 a1 = *reinterpret_cast<const float4*>(&Xs[k][64 + ty * 4]);
            float4 b0 = *reinterpret_cast<const float4*>(&Bs[k][tx * 4]);
            float4 b1 = *reinterpret_cast<const float4*>(&Bs[k][64 + tx * 4]);
            float a[8] = {a0.x, a0.y, a0.z, a0.w, a1.x, a1.y, a1.z, a1.w};
            float b[8] = {b0.x, b0.y, b0.z, b0.w, b1.x, b1.y, b1.z, b1.w};
            #pragma unroll
            for (int i = 0; i < 8; ++i)
                #pragma unroll
                for (int j = 0; j < 8; ++j)
                    acc[i][j] += a[i] * b[j];
        }
        __syncthreads();
    }

    // ---- epilogue: bias + store (rows ty*4.. and 64+ty*4..; cols tx*4.., 64+tx*4..)
    const int colA = c0 + tx * 4;
    const int colB = c0 + 64 + tx * 4;
    float4 bva = *reinterpret_cast<const float4*>(&bias[colA]);
    float4 bvb = *reinterpret_cast<const float4*>(&bias[colB]);

    #pragma unroll
    for (int ri = 0; ri < 2; ++ri) {
        #pragma unroll
        for (int i = 0; i < 4; ++i) {
            int r = m0 + ri * 64 + ty * 4 + i;
            int ai = ri * 4 + i;
            float4 o0 = make_float4(acc[ai][0] + bva.x, acc[ai][1] + bva.y,
                                    acc[ai][2] + bva.z, acc[ai][3] + bva.w);
            float4 o1 = make_float4(acc[ai][4] + bvb.x, acc[ai][5] + bvb.y,
                                    acc[ai][6] + bvb.z, acc[ai][7] + bvb.w);
            *reinterpret_cast<float4*>(&C[(size_t)r * Dc + colA]) = o0;
            *reinterpret_cast<float4*>(&C[(size_t)r * Dc + colB]) = o1;
        }
    }
}

// ---------------------------------------------------------------------------
// Kernel 2: causal flash attention, fp32, per (b,h), q-tiles of 64 rows.
// grid = (S/64, B*H), 256 threads, dynamic smem 4 * 64 * 68 floats.
// Q/K/V in [B,S,D] layout (head h = columns h*64..h*64+63, row stride Dc).
// Writes O directly in [B,S,D] layout (free head-concat).
// ---------------------------------------------------------------------------
__global__ __launch_bounds__(256) void attn_kernel()
{
    extern __shared__ float sm[];
    float* Qs  = sm;                // [64][68]  Q[row][e]
    float* Kst = sm + 64 * 68;      // [64][68]  K^T: [e][kj]
    float* Vs  = sm + 2 * 64 * 68;  // [64][68]  V[k][e]
    float* Ps  = sm + 3 * 64 * 68;  // [64][68]  P[row][k]

    // Reverse q-tile order: heaviest (most kv-iterations) blocks start first.
    const int bi = gridDim.x - 1 - blockIdx.x;
    const int bh = blockIdx.y;          // b*H + h
    const int bb = bh >> 4;
    const int h  = bh & 15;

    // [B,S,D] layout: base at (b, s=0, col=h*64); row stride = Dc.
    const float* qp = g_q + (size_t)bb * Sc * Dc + h * HDc;
    const float* kp = g_k + (size_t)bb * Sc * Dc + h * HDc;
    const float* vp = g_v + (size_t)bb * Sc * Dc + h * HDc;

    const int tid = threadIdx.x;
    const int ty = tid >> 4, tx = tid & 15;

    // Load Q tile (coalesced float4; 64-float row segments)
    #pragma unroll
    for (int r = 0; r < 4; ++r) {
        int idx = tid + r * 256;
        int i  = idx >> 4;
        int e4 = (idx & 15) * 4;
        float4 qv = *reinterpret_cast<const float4*>(&qp[(size_t)(bi * 64 + i) * Dc + e4]);
        *reinterpret_cast<float4*>(&Qs[i * 68 + e4]) = qv;
    }

    float m_i[4], l_i[4], acc[4][4] = {};
    #pragma unroll
    for (int i = 0; i < 4; ++i) { m_i[i] = -1e30f; l_i[i] = 0.0f; }

    for (int jb = 0; jb <= bi; ++jb) {
        __syncthreads();   // previous iteration's smem reads done (also Q visibility)
        // Load K (transposed into smem) and V
        #pragma unroll
        for (int r = 0; r < 4; ++r) {
            int idx = tid + r * 256;
            int kj = idx >> 4;
            int e4 = (idx & 15) * 4;
            float4 kv = *reinterpret_cast<const float4*>(&kp[(size_t)(jb * 64 + kj) * Dc + e4]);
            Kst[(e4 + 0) * 68 + kj] = kv.x;
            Kst[(e4 + 1) * 68 + kj] = kv.y;
            Kst[(e4 + 2) * 68 + kj] = kv.z;
            Kst[(e4 + 3) * 68 + kj] = kv.w;
            float4 vv = *reinterpret_cast<const float4*>(&vp[(size_t)(jb * 64 + kj) * Dc + e4]);
            *reinterpret_cast<float4*>(&Vs[kj * 68 + e4]) = vv;
        }
        __syncthreads();

        // S = Q K^T  (64x64x64)
        float s[4][4] = {};
        #pragma unroll 4
        for (int e = 0; e < 64; ++e) {
            float4 kv4 = *reinterpret_cast<const float4*>(&Kst[e * 68 + tx * 4]);
            float kb[4] = {kv4.x, kv4.y, kv4.z, kv4.w};
            #pragma unroll
            for (int i = 0; i < 4; ++i) {
                float qv = Qs[(ty * 4 + i) * 68 + e];
                #pragma unroll
                for (int j = 0; j < 4; ++j)
                    s[i][j] += qv * kb[j];
            }
        }

        // scale + causal mask
        #pragma unroll
        for (int i = 0; i < 4; ++i) {
            int qrow = bi * 64 + ty * 4 + i;
            #pragma unroll
            for (int j = 0; j < 4; ++j) {
                int krow = jb * 64 + tx * 4 + j;
                s[i][j] = (krow <= qrow) ? s[i][j] * 0.125f : -1e30f;
            }
        }

        // online softmax (row reductions across 16 tx lanes; lanes with equal
        // ty are contiguous 16-lane halves of a warp, xor<=8 stays inside)
        #pragma unroll
        for (int i = 0; i < 4; ++i) {
            float rmax = fmaxf(fmaxf(s[i][0], s[i][1]), fmaxf(s[i][2], s[i][3]));
            #pragma unroll
            for (int off = 8; off >= 1; off >>= 1)
                rmax = fmaxf(rmax, __shfl_xor_sync(0xffffffffu, rmax, off));
            float mnew = fmaxf(m_i[i], rmax);
            float corr = __expf(m_i[i] - mnew);
            m_i[i] = mnew;
            float rsum = 0.0f;
            #pragma unroll
            for (int j = 0; j < 4; ++j) { s[i][j] = __expf(s[i][j] - mnew); rsum += s[i][j]; }
            #pragma unroll
            for (int off = 8; off >= 1; off >>= 1)
                rsum += __shfl_xor_sync(0xffffffffu, rsum, off);
            l_i[i] = l_i[i] * corr + rsum;
            #pragma unroll
            for (int j = 0; j < 4; ++j) acc[i][j] *= corr;
        }

        // store P, then O += P V  (64x64x64)
        #pragma unroll
        for (int i = 0; i < 4; ++i)
            *reinterpret_cast<float4*>(&Ps[(ty * 4 + i) * 68 + tx * 4]) =
                make_float4(s[i][0], s[i][1], s[i][2], s[i][3]);
        __syncthreads();

        #pragma unroll 4
        for (int k = 0; k < 64; ++k) {
            float4 vv4 = *reinterpret_cast<const float4*>(&Vs[k * 68 + tx * 4]);
            float vb[4] = {vv4.x, vv4.y, vv4.z, vv4.w};
            #pragma unroll
            for (int i = 0; i < 4; ++i) {
                float pv = Ps[(ty * 4 + i) * 68 + k];
                #pragma unroll
                for (int j = 0; j < 4; ++j)
                    acc[i][j] += pv * vb[j];
            }
        }
    }

    // normalize + write O in [B,S,D]
    #pragma unroll
    for (int i = 0; i < 4; ++i) {
        int qrow = bi * 64 + ty * 4 + i;
        float inv = 1.0f / l_i[i];
        float4 r = make_float4(acc[i][0] * inv, acc[i][1] * inv,
                               acc[i][2] * inv, acc[i][3] * inv);
        *reinterpret_cast<float4*>(
            &g_o[((size_t)bb * Sc + qrow) * Dc + h * HDc + tx * 4]) = r;
    }
}

// ---------------------------------------------------------------------------
extern "C" void kernel_launch(void* const* d_in, const int* in_sizes, int n_in,
                              void* d_out, int out_size)
{
    const float* x  = (const float*)d_in[0];
    const float* Wq = (const float*)d_in[1];
    const float* bq = (const float*)d_in[2];
    const float* Wk = (const float*)d_in[3];
    const float* bk = (const float*)d_in[4];
    const float* Wv = (const float*)d_in[5];
    const float* bv = (const float*)d_in[6];
    const float* Wp = (const float*)d_in[7];
    const float* bp = (const float*)d_in[8];
    float* out = (float*)d_out;

    float* gq; cudaGetSymbolAddress((void**)&gq, g_q);
    float* gk; cudaGetSymbolAddress((void**)&gk, g_k);
    float* gv; cudaGetSymbolAddress((void**)&gv, g_v);
    float* go; cudaGetSymbolAddress((void**)&go, g_o);

    const size_t attn_smem = 4 * 64 * 68 * sizeof(float);  // 69632 B
    cudaFuncSetAttribute(attn_kernel,
                         cudaFuncAttributeMaxDynamicSharedMemorySize,
                         (int)attn_smem);

    const dim3 ggrid(Mrows / 128, Dc / 128);
    gemm_kernel<true><<<ggrid, 256>>>(x, Wq, bq, gq);
    gemm_kernel<true><<<ggrid, 256>>>(x, Wk, bk, gk);
    gemm_kernel<true><<<ggrid, 256>>>(x, Wv, bv, gv);
    attn_kernel<<<dim3(Sc / 64, Bc * Hc), 256, attn_smem>>>();
    gemm_kernel<false><<<ggrid, 256>>>(go, Wp, bp, out);
}

// round 15
// speedup vs baseline: 1.2855x; 1.2855x over previous
#include <cuda_runtime.h>
#include <cuda_bf16.h>
#include <math.h>

// Problem constants
constexpr int Bc  = 4;
constexpr int Sc  = 2048;
constexpr int Dc  = 1024;
constexpr int Hc  = 16;
constexpr int HDc = 64;
constexpr int Mrows = Bc * Sc;        // 8192
constexpr int NELEM = Mrows * Dc;     // 8388608

// fp32 scratch ([B,S,D] layout; head h = cols h*64..h*64+63)
__device__ float g_q[NELEM];
__device__ float g_k[NELEM];
__device__ float g_v[NELEM];
__device__ float g_o[NELEM];

// split-bf16 scratch
__device__ __nv_bfloat16 g_xhi[NELEM], g_xlo[NELEM];   // activations x
__device__ __nv_bfloat16 g_ohi[NELEM], g_olo[NELEM];   // attention output o
// weights, stored transposed+gathered: Bt[c][d] (contraction dim d contiguous)
__device__ __nv_bfloat16 g_wqh[Dc*Dc], g_wql[Dc*Dc];
__device__ __nv_bfloat16 g_wkh[Dc*Dc], g_wkl[Dc*Dc];
__device__ __nv_bfloat16 g_wvh[Dc*Dc], g_wvl[Dc*Dc];
__device__ __nv_bfloat16 g_wph[Dc*Dc], g_wpl[Dc*Dc];

// ---------------------------------------------------------------------------
// Split fp32 -> (hi, lo) bf16. 4 elems/thread, fully coalesced.
// ---------------------------------------------------------------------------
__device__ __forceinline__ unsigned bf16_bits(__nv_bfloat16 h) {
    return (unsigned)*reinterpret_cast<unsigned short*>(&h);
}

__global__ __launch_bounds__(256) void split_act(
    const float* __restrict__ in,
    __nv_bfloat16* __restrict__ hi, __nv_bfloat16* __restrict__ lo)
{
    int i = (blockIdx.x * 256 + threadIdx.x) * 4;
    float4 v4 = *reinterpret_cast<const float4*>(in + i);
    float v[4] = {v4.x, v4.y, v4.z, v4.w};
    unsigned hp[4], lp[4];
    #pragma unroll
    for (int j = 0; j < 4; ++j) {
        __nv_bfloat16 h = __float2bfloat16(v[j]);
        __nv_bfloat16 l = __float2bfloat16(v[j] - __bfloat162float(h));
        hp[j] = bf16_bits(h); lp[j] = bf16_bits(l);
    }
    uint2 ho = make_uint2(hp[0] | (hp[1] << 16), hp[2] | (hp[3] << 16));
    uint2 lo2 = make_uint2(lp[0] | (lp[1] << 16), lp[2] | (lp[3] << 16));
    *reinterpret_cast<uint2*>(reinterpret_cast<char*>(hi) + (size_t)i * 2) = ho;
    *reinterpret_cast<uint2*>(reinterpret_cast<char*>(lo) + (size_t)i * 2) = lo2;
}

// ---------------------------------------------------------------------------
// Split + gather weights into Bt[c][d].
// gather=1: Bt[c][d] = W[c>>6][d][c&63]   (W is [H][D][HD])
// gather=0: Bt[c][d] = Wp[d][c]           (Wp is [D][D] row-major)
// One elem/thread; writes coalesced over d.
// ---------------------------------------------------------------------------
__global__ __launch_bounds__(256) void split_w(
    const float* __restrict__ W,
    __nv_bfloat16* __restrict__ hi, __nv_bfloat16* __restrict__ lo, int gather)
{
    int idx = blockIdx.x * 256 + threadIdx.x;   // idx = c*1024 + d
    int c = idx >> 10, d = idx & 1023;
    float v = gather ? W[(size_t)(((c >> 6) << 10) + d) * 64 + (c & 63)]
                     : W[((size_t)d << 10) + c];
    __nv_bfloat16 h = __float2bfloat16(v);
    hi[idx] = h;
    lo[idx] = __float2bfloat16(v - __bfloat162float(h));
}

// ---------------------------------------------------------------------------
// Tensor-core GEMM: C[8192x1024] = A @ Bt^T + bias, split-bf16 3-product.
// Block 128m x 128n, 256 thr (8 warps = 2m x 4n), warp 64m x 32n.
// mma.sync m16n8k16 bf16, fp32 acc. K-chunk 32, double-buffered cp.async.
// grid = (64, 8)
// ---------------------------------------------------------------------------
__device__ __forceinline__ void mma16816(float* d, const unsigned* a, const unsigned* b) {
    asm volatile(
        "mma.sync.aligned.m16n8k16.row.col.f32.bf16.bf16.f32 "
        "{%0,%1,%2,%3}, {%4,%5,%6,%7}, {%8,%9}, {%0,%1,%2,%3};\n"
        : "+f"(d[0]), "+f"(d[1]), "+f"(d[2]), "+f"(d[3])
        : "r"(a[0]), "r"(a[1]), "r"(a[2]), "r"(a[3]), "r"(b[0]), "r"(b[1]));
}

__device__ __forceinline__ void cp16(void* smem_dst, const void* gsrc) {
    unsigned saddr = (unsigned)__cvta_generic_to_shared(smem_dst);
    asm volatile("cp.async.cg.shared.global [%0], [%1], 16;\n" :: "r"(saddr), "l"(gsrc));
}

constexpr int SMPAD = 40;              // row stride (bf16) -> 80B, conflict-free frags
constexpr int PLANE = 128 * SMPAD;     // elems per plane
constexpr int GEMM_SMEM = 2 * 4 * PLANE * 2;  // 81920 bytes

__global__ __launch_bounds__(256, 1) void mma_gemm(
    const __nv_bfloat16* __restrict__ Ahi, const __nv_bfloat16* __restrict__ Alo,
    const __nv_bfloat16* __restrict__ Bhi, const __nv_bfloat16* __restrict__ Blo,
    const float* __restrict__ bias, float* __restrict__ C)
{
    extern __shared__ __nv_bfloat16 sm[];   // [2 buf][4 plane][128][SMPAD]
    const int m0 = blockIdx.x * 128, c0 = blockIdx.y * 128;
    const int tid = threadIdx.x, warp = tid >> 5, lane = tid & 31;
    const int wm = (warp >> 2) * 64, wn = (warp & 3) * 32;
    const int g = lane >> 2, cq = lane & 3;

    const int lr  = tid >> 1;          // loader row 0..127
    const int lv0 = (tid & 1) * 2;     // loader 16B-vector index base

    float acc[4][4][4] = {};

    auto issue = [&](int kc) {
        const int k0 = kc * 32;
        __nv_bfloat16* s = sm + (kc & 1) * 4 * PLANE;
        const size_t arow = (size_t)(m0 + lr) * Dc + k0;
        const size_t brow = (size_t)(c0 + lr) * Dc + k0;
        #pragma unroll
        for (int u = 0; u < 2; ++u) {
            int v = lv0 + u;               // 0..3, k-offset v*8
            cp16(s + 0 * PLANE + lr * SMPAD + v * 8, Ahi + arow + v * 8);
            cp16(s + 1 * PLANE + lr * SMPAD + v * 8, Alo + arow + v * 8);
            cp16(s + 2 * PLANE + lr * SMPAD + v * 8, Bhi + brow + v * 8);
            cp16(s + 3 * PLANE + lr * SMPAD + v * 8, Blo + brow + v * 8);
        }
        asm volatile("cp.async.commit_group;\n");
    };

    issue(0);
    for (int kc = 0; kc < Dc / 32; ++kc) {
        if (kc + 1 < Dc / 32) { issue(kc + 1); asm volatile("cp.async.wait_group 1;\n"); }
        else                  { asm volatile("cp.async.wait_group 0;\n"); }
        __syncthreads();
        const __nv_bfloat16* s = sm + (kc & 1) * 4 * PLANE;

        #pragma unroll
        for (int ks = 0; ks < 32; ks += 16) {
            unsigned ah[4][4], al[4][4], bh[4][2], bl[4][2];
            #pragma unroll
            for (int mi = 0; mi < 4; ++mi) {
                int r0 = wm + mi * 16 + g;
                const __nv_bfloat16* ph = s + 0 * PLANE;
                const __nv_bfloat16* pl = s + 1 * PLANE;
                ah[mi][0] = *(const unsigned*)(ph + r0 * SMPAD + ks + 2 * cq);
                ah[mi][1] = *(const unsigned*)(ph + (r0 + 8) * SMPAD + ks + 2 * cq);
                ah[mi][2] = *(const unsigned*)(ph + r0 * SMPAD + ks + 2 * cq + 8);
                ah[mi][3] = *(const unsigned*)(ph + (r0 + 8) * SMPAD + ks + 2 * cq + 8);
                al[mi][0] = *(const unsigned*)(pl + r0 * SMPAD + ks + 2 * cq);
                al[mi][1] = *(const unsigned*)(pl + (r0 + 8) * SMPAD + ks + 2 * cq);
                al[mi][2] = *(const unsigned*)(pl + r0 * SMPAD + ks + 2 * cq + 8);
                al[mi][3] = *(const unsigned*)(pl + (r0 + 8) * SMPAD + ks + 2 * cq + 8);
            }
            #pragma unroll
            for (int ni = 0; ni < 4; ++ni) {
                int n0 = wn + ni * 8 + g;
                const __nv_bfloat16* ph = s + 2 * PLANE;
                const __nv_bfloat16* pl = s + 3 * PLANE;
                bh[ni][0] = *(const unsigned*)(ph + n0 * SMPAD + ks + 2 * cq);
                bh[ni][1] = *(const unsigned*)(ph + n0 * SMPAD + ks + 2 * cq + 8);
                bl[ni][0] = *(const unsigned*)(pl + n0 * SMPAD + ks + 2 * cq);
                bl[ni][1] = *(const unsigned*)(pl + n0 * SMPAD + ks + 2 * cq + 8);
            }
            #pragma unroll
            for (int mi = 0; mi < 4; ++mi)
                #pragma unroll
                for (int ni = 0; ni < 4; ++ni) {
                    mma16816(acc[mi][ni], ah[mi], bh[ni]);
                    mma16816(acc[mi][ni], ah[mi], bl[ni]);
                    mma16816(acc[mi][ni], al[mi], bh[ni]);
                }
        }
        __syncthreads();
    }

    // epilogue: bias + store
    #pragma unroll
    for (int mi = 0; mi < 4; ++mi) {
        int r0 = m0 + wm + mi * 16 + g;
        #pragma unroll
        for (int ni = 0; ni < 4; ++ni) {
            int col = c0 + wn + ni * 8 + 2 * cq;
            float b0 = bias[col], b1 = bias[col + 1];
            float2 v0 = make_float2(acc[mi][ni][0] + b0, acc[mi][ni][1] + b1);
            float2 v1 = make_float2(acc[mi][ni][2] + b0, acc[mi][ni][3] + b1);
            *reinterpret_cast<float2*>(&C[(size_t)r0 * Dc + col]) = v0;
            *reinterpret_cast<float2*>(&C[(size_t)(r0 + 8) * Dc + col]) = v1;
        }
    }
}

// ---------------------------------------------------------------------------
// Causal flash attention, fp32 (unchanged from passing round-14 baseline).
// grid = (S/64, B*H), 256 thr, dyn smem 4*64*68 floats.
// ---------------------------------------------------------------------------
__global__ __launch_bounds__(256) void attn_kernel()
{
    extern __shared__ float smf[];
    float* Qs  = smf;
    float* Kst = smf + 64 * 68;
    float* Vs  = smf + 2 * 64 * 68;
    float* Ps  = smf + 3 * 64 * 68;

    const int bi = gridDim.x - 1 - blockIdx.x;
    const int bh = blockIdx.y;
    const int bb = bh >> 4;
    const int h  = bh & 15;

    const float* qp = g_q + (size_t)bb * Sc * Dc + h * HDc;
    const float* kp = g_k + (size_t)bb * Sc * Dc + h * HDc;
    const float* vp = g_v + (size_t)bb * Sc * Dc + h * HDc;

    const int tid = threadIdx.x;
    const int ty = tid >> 4, tx = tid & 15;

    #pragma unroll
    for (int r = 0; r < 4; ++r) {
        int idx = tid + r * 256;
        int i  = idx >> 4;
        int e4 = (idx & 15) * 4;
        float4 qv = *reinterpret_cast<const float4*>(&qp[(size_t)(bi * 64 + i) * Dc + e4]);
        *reinterpret_cast<float4*>(&Qs[i * 68 + e4]) = qv;
    }

    float m_i[4], l_i[4], acc[4][4] = {};
    #pragma unroll
    for (int i = 0; i < 4; ++i) { m_i[i] = -1e30f; l_i[i] = 0.0f; }

    for (int jb = 0; jb <= bi; ++jb) {
        __syncthreads();
        #pragma unroll
        for (int r = 0; r < 4; ++r) {
            int idx = tid + r * 256;
            int kj = idx >> 4;
            int e4 = (idx & 15) * 4;
            float4 kv = *reinterpret_cast<const float4*>(&kp[(size_t)(jb * 64 + kj) * Dc + e4]);
            Kst[(e4 + 0) * 68 + kj] = kv.x;
            Kst[(e4 + 1) * 68 + kj] = kv.y;
            Kst[(e4 + 2) * 68 + kj] = kv.z;
            Kst[(e4 + 3) * 68 + kj] = kv.w;
            float4 vv = *reinterpret_cast<const float4*>(&vp[(size_t)(jb * 64 + kj) * Dc + e4]);
            *reinterpret_cast<float4*>(&Vs[kj * 68 + e4]) = vv;
        }
        __syncthreads();

        float s[4][4] = {};
        #pragma unroll 4
        for (int e = 0; e < 64; ++e) {
            float4 kv4 = *reinterpret_cast<const float4*>(&Kst[e * 68 + tx * 4]);
            float kb[4] = {kv4.x, kv4.y, kv4.z, kv4.w};
            #pragma unroll
            for (int i = 0; i < 4; ++i) {
                float qv = Qs[(ty * 4 + i) * 68 + e];
                #pragma unroll
                for (int j = 0; j < 4; ++j)
                    s[i][j] += qv * kb[j];
            }
        }

        #pragma unroll
        for (int i = 0; i < 4; ++i) {
            int qrow = bi * 64 + ty * 4 + i;
            #pragma unroll
            for (int j = 0; j < 4; ++j) {
                int krow = jb * 64 + tx * 4 + j;
                s[i][j] = (krow <= qrow) ? s[i][j] * 0.125f : -1e30f;
            }
        }

        #pragma unroll
        for (int i = 0; i < 4; ++i) {
            float rmax = fmaxf(fmaxf(s[i][0], s[i][1]), fmaxf(s[i][2], s[i][3]));
            #pragma unroll
            for (int off = 8; off >= 1; off >>= 1)
                rmax = fmaxf(rmax, __shfl_xor_sync(0xffffffffu, rmax, off));
            float mnew = fmaxf(m_i[i], rmax);
            float corr = __expf(m_i[i] - mnew);
            m_i[i] = mnew;
            float rsum = 0.0f;
            #pragma unroll
            for (int j = 0; j < 4; ++j) { s[i][j] = __expf(s[i][j] - mnew); rsum += s[i][j]; }
            #pragma unroll
            for (int off = 8; off >= 1; off >>= 1)
                rsum += __shfl_xor_sync(0xffffffffu, rsum, off);
            l_i[i] = l_i[i] * corr + rsum;
            #pragma unroll
            for (int j = 0; j < 4; ++j) acc[i][j] *= corr;
        }

        #pragma unroll
        for (int i = 0; i < 4; ++i)
            *reinterpret_cast<float4*>(&Ps[(ty * 4 + i) * 68 + tx * 4]) =
                make_float4(s[i][0], s[i][1], s[i][2], s[i][3]);
        __syncthreads();

        #pragma unroll 4
        for (int k = 0; k < 64; ++k) {
            float4 vv4 = *reinterpret_cast<const float4*>(&Vs[k * 68 + tx * 4]);
            float vb[4] = {vv4.x, vv4.y, vv4.z, vv4.w};
            #pragma unroll
            for (int i = 0; i < 4; ++i) {
                float pv = Ps[(ty * 4 + i) * 68 + k];
                #pragma unroll
                for (int j = 0; j < 4; ++j)
                    acc[i][j] += pv * vb[j];
            }
        }
    }

    #pragma unroll
    for (int i = 0; i < 4; ++i) {
        int qrow = bi * 64 + ty * 4 + i;
        float inv = 1.0f / l_i[i];
        float4 r = make_float4(acc[i][0] * inv, acc[i][1] * inv,
                               acc[i][2] * inv, acc[i][3] * inv);
        *reinterpret_cast<float4*>(
            &g_o[((size_t)bb * Sc + qrow) * Dc + h * HDc + tx * 4]) = r;
    }
}

// ---------------------------------------------------------------------------
extern "C" void kernel_launch(void* const* d_in, const int* in_sizes, int n_in,
                              void* d_out, int out_size)
{
    const float* x  = (const float*)d_in[0];
    const float* Wq = (const float*)d_in[1];
    const float* bq = (const float*)d_in[2];
    const float* Wk = (const float*)d_in[3];
    const float* bk = (const float*)d_in[4];
    const float* Wv = (const float*)d_in[5];
    const float* bv = (const float*)d_in[6];
    const float* Wp = (const float*)d_in[7];
    const float* bp = (const float*)d_in[8];
    float* out = (float*)d_out;

    float *gq, *gk, *gv, *go;
    cudaGetSymbolAddress((void**)&gq, g_q);
    cudaGetSymbolAddress((void**)&gk, g_k);
    cudaGetSymbolAddress((void**)&gv, g_v);
    cudaGetSymbolAddress((void**)&go, g_o);
    __nv_bfloat16 *xhi, *xlo, *ohi, *olo;
    cudaGetSymbolAddress((void**)&xhi, g_xhi);
    cudaGetSymbolAddress((void**)&xlo, g_xlo);
    cudaGetSymbolAddress((void**)&ohi, g_ohi);
    cudaGetSymbolAddress((void**)&olo, g_olo);
    __nv_bfloat16 *wqh, *wql, *wkh, *wkl, *wvh, *wvl, *wph, *wpl;
    cudaGetSymbolAddress((void**)&wqh, g_wqh);
    cudaGetSymbolAddress((void**)&wql, g_wql);
    cudaGetSymbolAddress((void**)&wkh, g_wkh);
    cudaGetSymbolAddress((void**)&wkl, g_wkl);
    cudaGetSymbolAddress((void**)&wvh, g_wvh);
    cudaGetSymbolAddress((void**)&wvl, g_wvl);
    cudaGetSymbolAddress((void**)&wph, g_wph);
    cudaGetSymbolAddress((void**)&wpl, g_wpl);

    cudaFuncSetAttribute(mma_gemm,
                         cudaFuncAttributeMaxDynamicSharedMemorySize, GEMM_SMEM);
    const size_t attn_smem = 4 * 64 * 68 * sizeof(float);  // 69632 B
    cudaFuncSetAttribute(attn_kernel,
                         cudaFuncAttributeMaxDynamicSharedMemorySize, (int)attn_smem);

    // 1) split inputs
    split_act<<<NELEM / 1024, 256>>>(x, xhi, xlo);
    split_w<<<Dc * Dc / 256, 256>>>(Wq, wqh, wql, 1);
    split_w<<<Dc * Dc / 256, 256>>>(Wk, wkh, wkl, 1);
    split_w<<<Dc * Dc / 256, 256>>>(Wv, wvh, wvl, 1);
    split_w<<<Dc * Dc / 256, 256>>>(Wp, wph, wpl, 0);

    // 2) QKV projections on tensor cores
    const dim3 ggrid(Mrows / 128, Dc / 128);
    mma_gemm<<<ggrid, 256, GEMM_SMEM>>>(xhi, xlo, wqh, wql, bq, gq);
    mma_gemm<<<ggrid, 256, GEMM_SMEM>>>(xhi, xlo, wkh, wkl, bk, gk);
    mma_gemm<<<ggrid, 256, GEMM_SMEM>>>(xhi, xlo, wvh, wvl, bv, gv);

    // 3) attention (fp32, unchanged)
    attn_kernel<<<dim3(Sc / 64, Bc * Hc), 256, attn_smem>>>();

    // 4) output projection on tensor cores
    split_act<<<NELEM / 1024, 256>>>(go, ohi, olo);
    mma_gemm<<<ggrid, 256, GEMM_SMEM>>>(ohi, olo, wph, wpl, bp, out);
}